// round 5
// baseline (speedup 1.0000x reference)
#include <cuda_runtime.h>
#include <cstdint>

#define DEV_INLINE __device__ __forceinline__

// ---------------------------------------------------------------------------
// Problem constants: B=4, T=2048, E=2048, H=16, KV=4, G=4, D=128
// ---------------------------------------------------------------------------

// Scratch (device-global: allocation-free per harness rules)
__device__ float g_Q [4 * 2048 * 2048];  // (B*T, H*D)   64 MB
__device__ float g_K [4 * 2048 * 512];   // (B*T, KV*D)  16 MB
__device__ float g_V [4 * 2048 * 512];   // (B*T, KV*D)  16 MB
__device__ float g_AY[4 * 2048 * 2048];  // (B*T, H*D)   64 MB

DEV_INLINE unsigned f2tf(float f) {
    unsigned u;
    asm("cvt.rna.tf32.f32 %0, %1;" : "=r"(u) : "f"(f));
    return u;
}
DEV_INLINE float tfr(float f) { return __uint_as_float(f2tf(f)); }

DEV_INLINE void mma8(float* c, const unsigned* a, const unsigned* b) {
    asm("mma.sync.aligned.m16n8k8.row.col.f32.tf32.tf32.f32 "
        "{%0,%1,%2,%3}, {%4,%5,%6,%7}, {%8,%9}, {%0,%1,%2,%3};"
        : "+f"(c[0]), "+f"(c[1]), "+f"(c[2]), "+f"(c[3])
        : "r"(a[0]), "r"(a[1]), "r"(a[2]), "r"(a[3]), "r"(b[0]), "r"(b[1]));
}

// ---------------------------------------------------------------------------
// tf32 GEMM: C(MxN) = A(MxK) @ B(KxN), all row-major. M from grid (128/CTA).
// BM=128 BN=128 BK=16; 256 threads = 8 warps in 2(m) x 4(n); warp tile 64x32.
// smem strides 20 / 136 chosen so fragment LDS are bank-conflict-free.
// ---------------------------------------------------------------------------
template <int N, int K>
__global__ __launch_bounds__(256) void gemm_tf32(const float* __restrict__ A,
                                                 const float* __restrict__ B,
                                                 float* __restrict__ C) {
    __shared__ float As[128][20];
    __shared__ float Bs[16][136];

    const int tid  = threadIdx.x;
    const int lane = tid & 31, wid = tid >> 5;
    const int g = lane >> 2, t = lane & 3;
    const int wm = wid & 1, wn = wid >> 1;
    const int bm = blockIdx.y * 128, bn = blockIdx.x * 128;

    float acc[4][4][4];
#pragma unroll
    for (int mi = 0; mi < 4; mi++)
#pragma unroll
        for (int ni = 0; ni < 4; ni++)
#pragma unroll
            for (int j = 0; j < 4; j++) acc[mi][ni][j] = 0.f;

    for (int k0 = 0; k0 < K; k0 += 16) {
        // A tile 128x16
#pragma unroll
        for (int i = 0; i < 2; i++) {
            int idx = tid * 2 + i;
            int r = idx >> 2, c4 = (idx & 3) << 2;
            float4 v = *(const float4*)(A + (size_t)(bm + r) * K + (k0 + c4));
            float4 w;
            w.x = tfr(v.x); w.y = tfr(v.y); w.z = tfr(v.z); w.w = tfr(v.w);
            *(float4*)&As[r][c4] = w;
        }
        // B tile 16x128
#pragma unroll
        for (int i = 0; i < 2; i++) {
            int idx = tid * 2 + i;
            int r = idx >> 5, c4 = (idx & 31) << 2;
            float4 v = *(const float4*)(B + (size_t)(k0 + r) * N + (bn + c4));
            float4 w;
            w.x = tfr(v.x); w.y = tfr(v.y); w.z = tfr(v.z); w.w = tfr(v.w);
            *(float4*)&Bs[r][c4] = w;
        }
        __syncthreads();

#pragma unroll
        for (int ks = 0; ks < 2; ks++) {
            const int kc = ks * 8;
            unsigned aF[4][4], bF[4][2];
#pragma unroll
            for (int mi = 0; mi < 4; mi++) {
                int r = wm * 64 + mi * 16;
                aF[mi][0] = __float_as_uint(As[r + g][kc + t]);
                aF[mi][1] = __float_as_uint(As[r + g + 8][kc + t]);
                aF[mi][2] = __float_as_uint(As[r + g][kc + t + 4]);
                aF[mi][3] = __float_as_uint(As[r + g + 8][kc + t + 4]);
            }
#pragma unroll
            for (int ni = 0; ni < 4; ni++) {
                int cN = wn * 32 + ni * 8 + g;
                bF[ni][0] = __float_as_uint(Bs[kc + t][cN]);
                bF[ni][1] = __float_as_uint(Bs[kc + t + 4][cN]);
            }
#pragma unroll
            for (int mi = 0; mi < 4; mi++)
#pragma unroll
                for (int ni = 0; ni < 4; ni++) mma8(acc[mi][ni], aF[mi], bF[ni]);
        }
        __syncthreads();
    }

#pragma unroll
    for (int mi = 0; mi < 4; mi++) {
        int r0 = bm + wm * 64 + mi * 16 + g;
#pragma unroll
        for (int ni = 0; ni < 4; ni++) {
            int cN = bn + wn * 32 + ni * 8 + 2 * t;
            *(float2*)(C + (size_t)r0 * N + cN) =
                make_float2(acc[mi][ni][0], acc[mi][ni][1]);
            *(float2*)(C + (size_t)(r0 + 8) * N + cN) =
                make_float2(acc[mi][ni][2], acc[mi][ni][3]);
        }
    }
}

// ---------------------------------------------------------------------------
// Flash attention (causal, GQA). Grid (T/64, H, B), 128 threads = 4 warps.
// Warp w owns 16 query rows. Key tiles of 32. tf32 mma for QK^T and PV.
// P re-fragmented via padded per-warp smem tile (C-layout != A-layout).
// ---------------------------------------------------------------------------
struct AttnSmem {
    float Qs[64][132];      // stride 132: frag loads conflict-free
    float Ks[32][132];
    float Vs[32][136];      // stride 136: B-frag loads conflict-free
    float Ps[4][16][36];    // per-warp P tile, stride 36
};

__global__ __launch_bounds__(128) void attn_flash(const float* __restrict__ Q,
                                                  const float* __restrict__ Kg,
                                                  const float* __restrict__ Vg,
                                                  float* __restrict__ Y) {
    extern __shared__ char smem_raw[];
    AttnSmem& S = *reinterpret_cast<AttnSmem*>(smem_raw);

    const int b = blockIdx.z, h = blockIdx.y, qb = blockIdx.x;
    const int kv = h >> 2;  // G = 4
    const int tid = threadIdx.x, w = tid >> 5, lane = tid & 31;
    const int g = lane >> 2, t = lane & 3;
    const float scale = 0.08838834764831845f;  // 1/sqrt(128)

    const float* Qb = Q + ((size_t)(b * 2048 + qb * 64)) * 2048 + h * 128;
    const float* Kb = Kg + ((size_t)b * 2048) * 512 + kv * 128;
    const float* Vb = Vg + ((size_t)b * 2048) * 512 + kv * 128;
    float* Yb = Y + ((size_t)(b * 2048 + qb * 64)) * 2048 + h * 128;

    // Stage Q block (64x128) into smem, tf32-rounded
#pragma unroll
    for (int i = 0; i < 16; i++) {
        int idx = i * 128 + tid;
        int r = idx >> 5, c4 = (idx & 31) << 2;
        float4 v = *(const float4*)(Qb + (size_t)r * 2048 + c4);
        float4 wv;
        wv.x = tfr(v.x); wv.y = tfr(v.y); wv.z = tfr(v.z); wv.w = tfr(v.w);
        *(float4*)&S.Qs[r][c4] = wv;
    }
    __syncthreads();

    // Q fragments live in registers for the whole CTA (16 k-steps x 4 regs)
    unsigned qF[16][4];
#pragma unroll
    for (int ks = 0; ks < 16; ks++) {
        int kc = ks * 8;
        int r = w * 16;
        qF[ks][0] = __float_as_uint(S.Qs[r + g][kc + t]);
        qF[ks][1] = __float_as_uint(S.Qs[r + g + 8][kc + t]);
        qF[ks][2] = __float_as_uint(S.Qs[r + g][kc + t + 4]);
        qF[ks][3] = __float_as_uint(S.Qs[r + g + 8][kc + t + 4]);
    }

    float O[16][4];
#pragma unroll
    for (int i = 0; i < 16; i++)
#pragma unroll
        for (int j = 0; j < 4; j++) O[i][j] = 0.f;
    float m0 = -1e30f, m1 = -1e30f, l0 = 0.f, l1 = 0.f;

    const int qr0 = qb * 64 + w * 16 + g;
    const int qr1 = qr0 + 8;
    const int qmaxw = qb * 64 + w * 16 + 15;
    const int ntiles = qb * 2 + 2;  // keys 0 .. qb*64+63

    for (int jt = 0; jt < ntiles; jt++) {
        const int jbase = jt * 32;
        __syncthreads();  // previous tile fully consumed
        // cooperative K/V tile load (32x128 each)
#pragma unroll
        for (int i = 0; i < 8; i++) {
            int idx = i * 128 + tid;
            int r = idx >> 5, c4 = (idx & 31) << 2;
            float4 kv4 = *(const float4*)(Kb + (size_t)(jbase + r) * 512 + c4);
            float4 w1;
            w1.x = tfr(kv4.x); w1.y = tfr(kv4.y); w1.z = tfr(kv4.z); w1.w = tfr(kv4.w);
            *(float4*)&S.Ks[r][c4] = w1;
            float4 vv4 = *(const float4*)(Vb + (size_t)(jbase + r) * 512 + c4);
            float4 w2;
            w2.x = tfr(vv4.x); w2.y = tfr(vv4.y); w2.z = tfr(vv4.z); w2.w = tfr(vv4.w);
            *(float4*)&S.Vs[r][c4] = w2;
        }
        __syncthreads();

        if (jbase > qmaxw) continue;  // tile fully masked for this warp

        // S = Q @ K^T  (16 x 32)
        float s[4][4];
#pragma unroll
        for (int ni = 0; ni < 4; ni++)
#pragma unroll
            for (int j = 0; j < 4; j++) s[ni][j] = 0.f;
#pragma unroll
        for (int ks = 0; ks < 16; ks++) {
#pragma unroll
            for (int ni = 0; ni < 4; ni++) {
                unsigned bK[2];
                bK[0] = __float_as_uint(S.Ks[ni * 8 + g][ks * 8 + t]);
                bK[1] = __float_as_uint(S.Ks[ni * 8 + g][ks * 8 + t + 4]);
                mma8(s[ni], qF[ks], bK);
            }
        }

        // scale + causal mask
#pragma unroll
        for (int ni = 0; ni < 4; ni++) {
            int col = jbase + ni * 8 + 2 * t;
            s[ni][0] = (col     <= qr0) ? s[ni][0] * scale : -1e30f;
            s[ni][1] = (col + 1 <= qr0) ? s[ni][1] * scale : -1e30f;
            s[ni][2] = (col     <= qr1) ? s[ni][2] * scale : -1e30f;
            s[ni][3] = (col + 1 <= qr1) ? s[ni][3] * scale : -1e30f;
        }

        // online softmax row statistics
        float tm0 = -1e30f, tm1 = -1e30f;
#pragma unroll
        for (int ni = 0; ni < 4; ni++) {
            tm0 = fmaxf(tm0, fmaxf(s[ni][0], s[ni][1]));
            tm1 = fmaxf(tm1, fmaxf(s[ni][2], s[ni][3]));
        }
        tm0 = fmaxf(tm0, __shfl_xor_sync(0xffffffffu, tm0, 1));
        tm0 = fmaxf(tm0, __shfl_xor_sync(0xffffffffu, tm0, 2));
        tm1 = fmaxf(tm1, __shfl_xor_sync(0xffffffffu, tm1, 1));
        tm1 = fmaxf(tm1, __shfl_xor_sync(0xffffffffu, tm1, 2));
        float nm0 = fmaxf(m0, tm0), nm1 = fmaxf(m1, tm1);
        float corr0 = __expf(m0 - nm0), corr1 = __expf(m1 - nm1);

        float ls0 = 0.f, ls1 = 0.f;
#pragma unroll
        for (int ni = 0; ni < 4; ni++) {
            s[ni][0] = __expf(s[ni][0] - nm0);
            s[ni][1] = __expf(s[ni][1] - nm0);
            s[ni][2] = __expf(s[ni][2] - nm1);
            s[ni][3] = __expf(s[ni][3] - nm1);
            ls0 += s[ni][0] + s[ni][1];
            ls1 += s[ni][2] + s[ni][3];
        }
        ls0 += __shfl_xor_sync(0xffffffffu, ls0, 1);
        ls0 += __shfl_xor_sync(0xffffffffu, ls0, 2);
        ls1 += __shfl_xor_sync(0xffffffffu, ls1, 1);
        ls1 += __shfl_xor_sync(0xffffffffu, ls1, 2);
        l0 = l0 * corr0 + ls0;
        l1 = l1 * corr1 + ls1;
        m0 = nm0;
        m1 = nm1;

        // rescale O accumulator
#pragma unroll
        for (int nf = 0; nf < 16; nf++) {
            O[nf][0] *= corr0; O[nf][1] *= corr0;
            O[nf][2] *= corr1; O[nf][3] *= corr1;
        }

        // P (C-layout) -> per-warp smem -> A-layout fragments
#pragma unroll
        for (int ni = 0; ni < 4; ni++) {
            *(float2*)&S.Ps[w][g][ni * 8 + 2 * t] =
                make_float2(__uint_as_float(f2tf(s[ni][0])),
                            __uint_as_float(f2tf(s[ni][1])));
            *(float2*)&S.Ps[w][g + 8][ni * 8 + 2 * t] =
                make_float2(__uint_as_float(f2tf(s[ni][2])),
                            __uint_as_float(f2tf(s[ni][3])));
        }
        __syncwarp();

        // O += P @ V   (16x32 @ 32x128)
#pragma unroll
        for (int ks2 = 0; ks2 < 4; ks2++) {
            unsigned aP[4];
            aP[0] = __float_as_uint(S.Ps[w][g][ks2 * 8 + t]);
            aP[1] = __float_as_uint(S.Ps[w][g + 8][ks2 * 8 + t]);
            aP[2] = __float_as_uint(S.Ps[w][g][ks2 * 8 + t + 4]);
            aP[3] = __float_as_uint(S.Ps[w][g + 8][ks2 * 8 + t + 4]);
#pragma unroll
            for (int nf = 0; nf < 16; nf++) {
                unsigned bV[2];
                bV[0] = __float_as_uint(S.Vs[ks2 * 8 + t][nf * 8 + g]);
                bV[1] = __float_as_uint(S.Vs[ks2 * 8 + t + 4][nf * 8 + g]);
                mma8(O[nf], aP, bV);
            }
        }
    }

    // epilogue: normalize and store
    float inv0 = 1.f / l0, inv1 = 1.f / l1;
#pragma unroll
    for (int nf = 0; nf < 16; nf++) {
        int cN = nf * 8 + 2 * t;
        *(float2*)(Yb + (size_t)(w * 16 + g) * 2048 + cN) =
            make_float2(O[nf][0] * inv0, O[nf][1] * inv0);
        *(float2*)(Yb + (size_t)(w * 16 + g + 8) * 2048 + cN) =
            make_float2(O[nf][2] * inv1, O[nf][3] * inv1);
    }
}

// ---------------------------------------------------------------------------
// Launch
// ---------------------------------------------------------------------------
extern "C" void kernel_launch(void* const* d_in, const int* in_sizes, int n_in,
                              void* d_out, int out_size) {
    (void)in_sizes; (void)n_in; (void)out_size;
    const float* x  = (const float*)d_in[0];
    const float* Wq = (const float*)d_in[1];
    const float* Wk = (const float*)d_in[2];
    const float* Wv = (const float*)d_in[3];
    const float* Wo = (const float*)d_in[4];
    float* out = (float*)d_out;

    float *Qp, *Kp, *Vp, *AYp;
    cudaGetSymbolAddress((void**)&Qp, g_Q);
    cudaGetSymbolAddress((void**)&Kp, g_K);
    cudaGetSymbolAddress((void**)&Vp, g_V);
    cudaGetSymbolAddress((void**)&AYp, g_AY);

    // Stage 1: QKV projections (M=8192, K=2048)
    gemm_tf32<2048, 2048><<<dim3(16, 64), 256>>>(x, Wq, Qp);
    gemm_tf32<512, 2048><<<dim3(4, 64), 256>>>(x, Wk, Kp);
    gemm_tf32<512, 2048><<<dim3(4, 64), 256>>>(x, Wv, Vp);

    // Stage 2: causal GQA flash attention
    cudaFuncSetAttribute(attn_flash, cudaFuncAttributeMaxDynamicSharedMemorySize,
                         (int)sizeof(AttnSmem));
    attn_flash<<<dim3(32, 16, 4), 128, sizeof(AttnSmem)>>>(Qp, Kp, Vp, AYp);

    // Stage 3: output projection
    gemm_tf32<2048, 2048><<<dim3(16, 64), 256>>>(AYp, Wo, out);
}

// round 6
// speedup vs baseline: 1.4950x; 1.4950x over previous
#include <cuda_runtime.h>
#include <cuda_fp16.h>
#include <cstdint>

#define DEV_INLINE __device__ __forceinline__

// ---------------------------------------------------------------------------
// Problem constants: B=4, T=2048, E=2048, H=16, KV=4, G=4, D=128
// ---------------------------------------------------------------------------

// Scratch (device-global: allocation-free per harness rules)
__device__ __half g_Qh[4 * 2048 * 2048];     // (B*T, H*D)    32 MB
__device__ __half g_Kh[4 * 2048 * 512];      // (B*T, KV*D)    8 MB
__device__ __half g_Vh[4 * 2048 * 512];      // (B*T, KV*D)    8 MB
__device__ __half g_Vt[4 * 4 * 128 * 2048];  // (B,KV,D,T)     8 MB
__device__ float  g_AY[4 * 2048 * 2048];     // (B*T, H*D)    64 MB

DEV_INLINE uint32_t packh2(float lo, float hi) {
    __half2 h = __floats2half2_rn(lo, hi);
    return *reinterpret_cast<uint32_t*>(&h);
}

DEV_INLINE void mma16(float* c, const uint32_t* a, const uint32_t* b) {
    asm("mma.sync.aligned.m16n8k16.row.col.f32.f16.f16.f32 "
        "{%0,%1,%2,%3}, {%4,%5,%6,%7}, {%8,%9}, {%0,%1,%2,%3};"
        : "+f"(c[0]), "+f"(c[1]), "+f"(c[2]), "+f"(c[3])
        : "r"(a[0]), "r"(a[1]), "r"(a[2]), "r"(a[3]), "r"(b[0]), "r"(b[1]));
}

// ---------------------------------------------------------------------------
// fp16 GEMM, f32 in / (half|f32) out: C(MxN) = A(MxK) @ B(KxN), row-major.
// BM=128 BN=128 BK=32; 256 threads = 8 warps (2m x 4n); warp tile 64x32.
// Double-buffered smem with register prefetch.
// smem in uint32 (half2-along-K) units: As[m][kp], Bs[n][kp ^ ((n>>3)&3)].
// Stride 20 units -> all fragment LDS.32 bank-conflict-free.
// ---------------------------------------------------------------------------
template <int N, int K, bool HALF_OUT>
__global__ __launch_bounds__(256) void gemm_f16(const float* __restrict__ A,
                                                const float* __restrict__ Bm,
                                                void* __restrict__ Cv) {
    __shared__ uint32_t AsU[2][128][20];
    __shared__ uint32_t BsU[2][128][20];

    const int tid = threadIdx.x;
    const int lane = tid & 31, wid = tid >> 5;
    const int g = lane >> 2, t = lane & 3;
    const int wm = wid & 1, wn = wid >> 1;
    const int bm = blockIdx.y * 128, bn = blockIdx.x * 128;

    // loader mapping
    const int a_row = tid >> 4;                               // 0..15 (+ i*16)
    const int a_kp  = tid & 15;                               // half2 unit in BK
    const int b_n   = (tid & 31) | (((tid >> 5) & 3) << 5);   // 0..127
    const int b_kp0 = (tid >> 7) << 3;                        // 0 or 8
    const int b_x   = (b_n >> 3) & 3;                         // store-side swizzle

    float acc[4][4][4];
#pragma unroll
    for (int mi = 0; mi < 4; mi++)
#pragma unroll
        for (int ni = 0; ni < 4; ni++)
#pragma unroll
            for (int j = 0; j < 4; j++) acc[mi][ni][j] = 0.f;

    float2 pa[8];
    float  pb0[8], pb1[8];

    const float* Abase = A + (size_t)(bm + a_row) * K + 2 * a_kp;
    const float* Bbase = Bm + (size_t)bn + b_n;

    // prologue: tile 0 -> regs -> smem buf 0
#pragma unroll
    for (int i = 0; i < 8; i++)
        pa[i] = *(const float2*)(Abase + (size_t)i * 16 * K);
#pragma unroll
    for (int i = 0; i < 8; i++) {
        int kk = 2 * (b_kp0 + i);
        pb0[i] = Bbase[(size_t)kk * N];
        pb1[i] = Bbase[(size_t)(kk + 1) * N];
    }
#pragma unroll
    for (int i = 0; i < 8; i++)
        AsU[0][a_row + i * 16][a_kp] = packh2(pa[i].x, pa[i].y);
#pragma unroll
    for (int i = 0; i < 8; i++)
        BsU[0][b_n][(b_kp0 + i) ^ b_x] = packh2(pb0[i], pb1[i]);
    __syncthreads();

    const int NT = K / 32;
    for (int kt = 0; kt < NT; kt++) {
        const int cur = kt & 1;
        if (kt + 1 < NT) {
            const float* Ab = Abase + (kt + 1) * 32;
#pragma unroll
            for (int i = 0; i < 8; i++)
                pa[i] = *(const float2*)(Ab + (size_t)i * 16 * K);
            const float* Bb = Bbase + (size_t)(kt + 1) * 32 * N;
#pragma unroll
            for (int i = 0; i < 8; i++) {
                int kk = 2 * (b_kp0 + i);
                pb0[i] = Bb[(size_t)kk * N];
                pb1[i] = Bb[(size_t)(kk + 1) * N];
            }
        }

#pragma unroll
        for (int ks = 0; ks < 2; ks++) {
            uint32_t aF[4][4];
#pragma unroll
            for (int mi = 0; mi < 4; mi++) {
                int r = wm * 64 + mi * 16;
                aF[mi][0] = AsU[cur][r + g][ks * 8 + t];
                aF[mi][1] = AsU[cur][r + g + 8][ks * 8 + t];
                aF[mi][2] = AsU[cur][r + g][ks * 8 + t + 4];
                aF[mi][3] = AsU[cur][r + g + 8][ks * 8 + t + 4];
            }
#pragma unroll
            for (int ni = 0; ni < 4; ni++) {
                int n = wn * 32 + ni * 8 + g;
                int x = (n >> 3) & 3;
                uint32_t bF[2];
                bF[0] = BsU[cur][n][(ks * 8 + t) ^ x];
                bF[1] = BsU[cur][n][(ks * 8 + t + 4) ^ x];
#pragma unroll
                for (int mi = 0; mi < 4; mi++) mma16(acc[mi][ni], aF[mi], bF);
            }
        }

        if (kt + 1 < NT) {
            const int nxt = cur ^ 1;
#pragma unroll
            for (int i = 0; i < 8; i++)
                AsU[nxt][a_row + i * 16][a_kp] = packh2(pa[i].x, pa[i].y);
#pragma unroll
            for (int i = 0; i < 8; i++)
                BsU[nxt][b_n][(b_kp0 + i) ^ b_x] = packh2(pb0[i], pb1[i]);
        }
        __syncthreads();
    }

    // epilogue
#pragma unroll
    for (int mi = 0; mi < 4; mi++) {
        int r0 = bm + wm * 64 + mi * 16 + g;
#pragma unroll
        for (int ni = 0; ni < 4; ni++) {
            int cN = bn + wn * 32 + ni * 8 + 2 * t;
            if (HALF_OUT) {
                __half* C = (__half*)Cv;
                *reinterpret_cast<__half2*>(C + (size_t)r0 * N + cN) =
                    __floats2half2_rn(acc[mi][ni][0], acc[mi][ni][1]);
                *reinterpret_cast<__half2*>(C + (size_t)(r0 + 8) * N + cN) =
                    __floats2half2_rn(acc[mi][ni][2], acc[mi][ni][3]);
            } else {
                float* C = (float*)Cv;
                *(float2*)(C + (size_t)r0 * N + cN) =
                    make_float2(acc[mi][ni][0], acc[mi][ni][1]);
                *(float2*)(C + (size_t)(r0 + 8) * N + cN) =
                    make_float2(acc[mi][ni][2], acc[mi][ni][3]);
            }
        }
    }
}

// ---------------------------------------------------------------------------
// V transpose: g_Vh (B*T, KV*D) half -> g_Vt (B,KV,D,T) half.
// Output unit (d, kp) = half2(V[2kp][d], V[2kp+1][d]) — key-pair packed,
// exactly the B-fragment layout the P@V mma wants.
// Grid (32, 8, 4), 256 threads: 64-key x 64-d tiles. ~16 MB traffic.
// ---------------------------------------------------------------------------
__global__ __launch_bounds__(256) void transpose_v(const __half* __restrict__ Vh,
                                                   __half* __restrict__ Vt) {
    __shared__ uint32_t U[64][33];
    const int tid = threadIdx.x;
    const int k0 = blockIdx.x * 64;
    const int kv = blockIdx.y >> 1;
    const int d0 = (blockIdx.y & 1) * 64;
    const int b  = blockIdx.z;

    const uint32_t* in = reinterpret_cast<const uint32_t*>(Vh);
    {
        int dp = tid & 31;        // d-pair 0..31 (covers d0..d0+63)
        int krow = tid >> 5;      // 0..7
#pragma unroll
        for (int i = 0; i < 8; i++) {
            int key = i * 8 + krow;
            U[key][dp] =
                in[(size_t)(b * 2048 + k0 + key) * 256 + kv * 64 + (d0 >> 1) + dp];
        }
    }
    __syncthreads();
    uint32_t* out = reinterpret_cast<uint32_t*>(Vt);
    {
        int kp = tid & 31;        // key-pair within tile
        int drow = tid >> 5;
#pragma unroll
        for (int i = 0; i < 8; i++) {
            int d = i * 8 + drow;
            uint32_t a = U[2 * kp][d >> 1];
            uint32_t c = U[2 * kp + 1][d >> 1];
            uint32_t lo = (d & 1) ? (a >> 16) : (a & 0xffffu);
            uint32_t hi = (d & 1) ? (c >> 16) : (c & 0xffffu);
            out[(size_t)((b * 4 + kv) * 128 + d0 + d) * 1024 + (k0 >> 1) + kp] =
                lo | (hi << 16);
        }
    }
}

// ---------------------------------------------------------------------------
// Flash attention (causal, GQA), fp16 m16n8k16 core, f32 softmax/accum.
// Grid (T/64, H, B), 128 threads = 4 warps; warp owns 16 query rows.
// smem in half2 units; every fragment LDS bank-conflict-free (strides 68/20).
// ---------------------------------------------------------------------------
struct AttnSmemH {
    uint32_t Qs[64][68];    // (row, d-pair)        17.4 KB
    uint32_t Ks[32][68];    // (key, d-pair)         8.7 KB
    uint32_t Vs[128][20];   // (d,  key-pair)       10.2 KB
    uint32_t Ps[4][16][20]; // per-warp P tile       5.1 KB
};

__global__ __launch_bounds__(128) void attn_f16(const __half* __restrict__ Qh,
                                                const __half* __restrict__ Kh,
                                                const __half* __restrict__ Vt,
                                                float* __restrict__ Y) {
    __shared__ AttnSmemH S;

    const int b = blockIdx.z, h = blockIdx.y, qb = blockIdx.x;
    const int kv = h >> 2;  // G = 4
    const int tid = threadIdx.x, w = tid >> 5, lane = tid & 31;
    const int g = lane >> 2, t = lane & 3;
    const float scale = 0.08838834764831845f;  // 1/sqrt(128)

    const uint32_t* Qu = reinterpret_cast<const uint32_t*>(Qh);
    const uint32_t* Ku = reinterpret_cast<const uint32_t*>(Kh);
    const uint32_t* Vu = reinterpret_cast<const uint32_t*>(Vt);

    // Stage Q block: 64 rows x 64 half2-units
#pragma unroll
    for (int i = 0; i < 16; i++) {
        int r = i * 4 + w;
        const uint32_t* qrow = Qu + (size_t)(b * 2048 + qb * 64 + r) * 1024 + h * 64;
        S.Qs[r][lane]      = qrow[lane];
        S.Qs[r][lane + 32] = qrow[lane + 32];
    }
    __syncthreads();

    // Q fragments register-resident: 8 k16-steps x 4 regs
    uint32_t qF[8][4];
#pragma unroll
    for (int ks = 0; ks < 8; ks++) {
        int r = w * 16;
        qF[ks][0] = S.Qs[r + g][ks * 8 + t];
        qF[ks][1] = S.Qs[r + g + 8][ks * 8 + t];
        qF[ks][2] = S.Qs[r + g][ks * 8 + t + 4];
        qF[ks][3] = S.Qs[r + g + 8][ks * 8 + t + 4];
    }

    float O[16][4];
#pragma unroll
    for (int i = 0; i < 16; i++)
#pragma unroll
        for (int j = 0; j < 4; j++) O[i][j] = 0.f;
    float m0 = -1e30f, m1 = -1e30f, l0 = 0.f, l1 = 0.f;

    const int qr0 = qb * 64 + w * 16 + g;
    const int qr1 = qr0 + 8;
    const int qmaxw = qb * 64 + w * 16 + 15;
    const int ntiles = qb * 2 + 2;  // keys 0 .. qb*64+63

    for (int jt = 0; jt < ntiles; jt++) {
        const int jbase = jt * 32;
        __syncthreads();  // previous tile fully consumed
        // K tile: 32 keys x 64 units
#pragma unroll
        for (int i = 0; i < 8; i++) {
            int r = i * 4 + w;
            const uint32_t* krow =
                Ku + (size_t)(b * 2048 + jbase + r) * 256 + kv * 64;
            S.Ks[r][lane]      = krow[lane];
            S.Ks[r][lane + 32] = krow[lane + 32];
        }
        // V tile (transposed): 128 d-rows x 16 key-pair units
#pragma unroll
        for (int i = 0; i < 16; i++) {
            int d = i * 8 + w * 2 + (lane >> 4);
            const uint32_t* vrow =
                Vu + (size_t)((b * 4 + kv) * 128 + d) * 1024 + (jbase >> 1);
            S.Vs[d][lane & 15] = vrow[lane & 15];
        }
        __syncthreads();

        if (jbase > qmaxw) continue;  // tile fully masked for this warp

        // S = Q @ K^T  (16 x 32), 8 k16-steps
        float s[4][4];
#pragma unroll
        for (int ni = 0; ni < 4; ni++)
#pragma unroll
            for (int j = 0; j < 4; j++) s[ni][j] = 0.f;
#pragma unroll
        for (int ks = 0; ks < 8; ks++) {
#pragma unroll
            for (int ni = 0; ni < 4; ni++) {
                uint32_t bK[2];
                bK[0] = S.Ks[ni * 8 + g][ks * 8 + t];
                bK[1] = S.Ks[ni * 8 + g][ks * 8 + t + 4];
                mma16(s[ni], qF[ks], bK);
            }
        }

        // scale + causal mask
#pragma unroll
        for (int ni = 0; ni < 4; ni++) {
            int col = jbase + ni * 8 + 2 * t;
            s[ni][0] = (col     <= qr0) ? s[ni][0] * scale : -1e30f;
            s[ni][1] = (col + 1 <= qr0) ? s[ni][1] * scale : -1e30f;
            s[ni][2] = (col     <= qr1) ? s[ni][2] * scale : -1e30f;
            s[ni][3] = (col + 1 <= qr1) ? s[ni][3] * scale : -1e30f;
        }

        // online softmax row statistics
        float tm0 = -1e30f, tm1 = -1e30f;
#pragma unroll
        for (int ni = 0; ni < 4; ni++) {
            tm0 = fmaxf(tm0, fmaxf(s[ni][0], s[ni][1]));
            tm1 = fmaxf(tm1, fmaxf(s[ni][2], s[ni][3]));
        }
        tm0 = fmaxf(tm0, __shfl_xor_sync(0xffffffffu, tm0, 1));
        tm0 = fmaxf(tm0, __shfl_xor_sync(0xffffffffu, tm0, 2));
        tm1 = fmaxf(tm1, __shfl_xor_sync(0xffffffffu, tm1, 1));
        tm1 = fmaxf(tm1, __shfl_xor_sync(0xffffffffu, tm1, 2));
        float nm0 = fmaxf(m0, tm0), nm1 = fmaxf(m1, tm1);
        float corr0 = __expf(m0 - nm0), corr1 = __expf(m1 - nm1);

        float ls0 = 0.f, ls1 = 0.f;
#pragma unroll
        for (int ni = 0; ni < 4; ni++) {
            s[ni][0] = __expf(s[ni][0] - nm0);
            s[ni][1] = __expf(s[ni][1] - nm0);
            s[ni][2] = __expf(s[ni][2] - nm1);
            s[ni][3] = __expf(s[ni][3] - nm1);
            ls0 += s[ni][0] + s[ni][1];
            ls1 += s[ni][2] + s[ni][3];
        }
        ls0 += __shfl_xor_sync(0xffffffffu, ls0, 1);
        ls0 += __shfl_xor_sync(0xffffffffu, ls0, 2);
        ls1 += __shfl_xor_sync(0xffffffffu, ls1, 1);
        ls1 += __shfl_xor_sync(0xffffffffu, ls1, 2);
        l0 = l0 * corr0 + ls0;
        l1 = l1 * corr1 + ls1;
        m0 = nm0;
        m1 = nm1;

        // rescale O accumulator
#pragma unroll
        for (int nf = 0; nf < 16; nf++) {
            O[nf][0] *= corr0; O[nf][1] *= corr0;
            O[nf][2] *= corr1; O[nf][3] *= corr1;
        }

        // P (C-layout) -> per-warp smem (half2 key-pairs) -> A-layout frags
#pragma unroll
        for (int ni = 0; ni < 4; ni++) {
            S.Ps[w][g][ni * 4 + t]     = packh2(s[ni][0], s[ni][1]);
            S.Ps[w][g + 8][ni * 4 + t] = packh2(s[ni][2], s[ni][3]);
        }
        __syncwarp();

        // O += P @ V   (16x32 @ 32x128), 2 k16-steps
#pragma unroll
        for (int ks2 = 0; ks2 < 2; ks2++) {
            uint32_t aP[4];
            aP[0] = S.Ps[w][g][ks2 * 8 + t];
            aP[1] = S.Ps[w][g + 8][ks2 * 8 + t];
            aP[2] = S.Ps[w][g][ks2 * 8 + t + 4];
            aP[3] = S.Ps[w][g + 8][ks2 * 8 + t + 4];
#pragma unroll
            for (int nf = 0; nf < 16; nf++) {
                uint32_t bV[2];
                bV[0] = S.Vs[nf * 8 + g][ks2 * 8 + t];
                bV[1] = S.Vs[nf * 8 + g][ks2 * 8 + t + 4];
                mma16(O[nf], aP, bV);
            }
        }
    }

    // epilogue: normalize and store (f32 — feeds the out-projection GEMM)
    float* Yb = Y + ((size_t)(b * 2048 + qb * 64)) * 2048 + h * 128;
    float inv0 = 1.f / l0, inv1 = 1.f / l1;
#pragma unroll
    for (int nf = 0; nf < 16; nf++) {
        int cN = nf * 8 + 2 * t;
        *(float2*)(Yb + (size_t)(w * 16 + g) * 2048 + cN) =
            make_float2(O[nf][0] * inv0, O[nf][1] * inv0);
        *(float2*)(Yb + (size_t)(w * 16 + g + 8) * 2048 + cN) =
            make_float2(O[nf][2] * inv1, O[nf][3] * inv1);
    }
}

// ---------------------------------------------------------------------------
// Launch
// ---------------------------------------------------------------------------
extern "C" void kernel_launch(void* const* d_in, const int* in_sizes, int n_in,
                              void* d_out, int out_size) {
    (void)in_sizes; (void)n_in; (void)out_size;
    const float* x  = (const float*)d_in[0];
    const float* Wq = (const float*)d_in[1];
    const float* Wk = (const float*)d_in[2];
    const float* Wv = (const float*)d_in[3];
    const float* Wo = (const float*)d_in[4];
    float* out = (float*)d_out;

    __half *Qp, *Kp, *Vp, *Vtp;
    float* AYp;
    cudaGetSymbolAddress((void**)&Qp, g_Qh);
    cudaGetSymbolAddress((void**)&Kp, g_Kh);
    cudaGetSymbolAddress((void**)&Vp, g_Vh);
    cudaGetSymbolAddress((void**)&Vtp, g_Vt);
    cudaGetSymbolAddress((void**)&AYp, g_AY);

    // Stage 1: QKV projections (M=8192, K=2048), half outputs
    gemm_f16<2048, 2048, true><<<dim3(16, 64), 256>>>(x, Wq, Qp);
    gemm_f16<512, 2048, true><<<dim3(4, 64), 256>>>(x, Wk, Kp);
    gemm_f16<512, 2048, true><<<dim3(4, 64), 256>>>(x, Wv, Vp);

    // Stage 1b: transpose V into (B,KV,D,T) key-pair-packed layout
    transpose_v<<<dim3(32, 8, 4), 256>>>(Vp, Vtp);

    // Stage 2: causal GQA flash attention (fp16 core, f32 softmax)
    attn_f16<<<dim3(32, 16, 4), 128>>>(Qp, Kp, Vtp, AYp);

    // Stage 3: output projection (f32 in, f32 out)
    gemm_f16<2048, 2048, false><<<dim3(16, 64), 256>>>(AYp, Wo, out);
}

// round 7
// speedup vs baseline: 1.6870x; 1.1284x over previous
#include <cuda_runtime.h>
#include <cuda_fp16.h>
#include <cstdint>

#define DEV_INLINE __device__ __forceinline__

// ---------------------------------------------------------------------------
// Problem constants: B=4, T=2048, E=2048, H=16, KV=4, G=4, D=128
// ---------------------------------------------------------------------------

// Scratch (device-global: allocation-free per harness rules)
__device__ __half g_xh [4 * 2048 * 2048];     // x   half          32 MB
__device__ __half g_Wqt[2048 * 2048];         // Wq^T (N,K) half    8 MB
__device__ __half g_Wkt[512 * 2048];          // Wk^T               2 MB
__device__ __half g_Wvt[512 * 2048];          // Wv^T               2 MB
__device__ __half g_Wot[2048 * 2048];         // Wo^T               8 MB
__device__ __half g_Qh [4 * 2048 * 2048];     // (B*T, H*D)        32 MB
__device__ __half g_Kh [4 * 2048 * 512];      // (B*T, KV*D)        8 MB
__device__ __half g_Vh [4 * 2048 * 512];      // (B*T, KV*D)        8 MB
__device__ __half g_Vt [4 * 4 * 128 * 2048];  // (B,KV,D,T)         8 MB
__device__ __half g_AYh[4 * 2048 * 2048];     // attn out half     32 MB

DEV_INLINE uint32_t packh2(float lo, float hi) {
    __half2 h = __floats2half2_rn(lo, hi);
    return *reinterpret_cast<uint32_t*>(&h);
}

DEV_INLINE void mma16(float* c, const uint32_t* a, const uint32_t* b) {
    asm("mma.sync.aligned.m16n8k16.row.col.f32.f16.f16.f32 "
        "{%0,%1,%2,%3}, {%4,%5,%6,%7}, {%8,%9}, {%0,%1,%2,%3};"
        : "+f"(c[0]), "+f"(c[1]), "+f"(c[2]), "+f"(c[3])
        : "r"(a[0]), "r"(a[1]), "r"(a[2]), "r"(a[3]), "r"(b[0]), "r"(b[1]));
}

DEV_INLINE uint32_t sptr(const void* p) {
    return (uint32_t)__cvta_generic_to_shared(p);
}
DEV_INLINE void cp16(uint32_t dst, const void* src) {
    asm volatile("cp.async.cg.shared.global [%0], [%1], 16;" ::
                     "r"(dst), "l"(src));
}

// ---------------------------------------------------------------------------
// Prep kernels
// ---------------------------------------------------------------------------
__global__ __launch_bounds__(256) void f2h_kernel(const float* __restrict__ in,
                                                  __half* __restrict__ out) {
    int i = (blockIdx.x * 256 + threadIdx.x) * 4;
    float4 v = *(const float4*)(in + i);
    uint2 o;
    o.x = packh2(v.x, v.y);
    o.y = packh2(v.z, v.w);
    *(uint2*)(out + i) = o;
}

// W (K=2048, N) f32 -> Wt (N, K=2048) half. Tile 32x32, block 256.
__global__ __launch_bounds__(256) void transpose_w(const float* __restrict__ W,
                                                   __half* __restrict__ Wt,
                                                   int Ncols) {
    __shared__ float t[32][33];
    const int n0 = blockIdx.x * 32, k0 = blockIdx.y * 32;
    const int lx = threadIdx.x & 31, ly = threadIdx.x >> 5;  // ly 0..7
#pragma unroll
    for (int i = 0; i < 4; i++)
        t[ly + 8 * i][lx] = W[(size_t)(k0 + ly + 8 * i) * Ncols + n0 + lx];
    __syncthreads();
#pragma unroll
    for (int i = 0; i < 4; i++)
        Wt[(size_t)(n0 + ly + 8 * i) * 2048 + k0 + lx] =
            __float2half(t[lx][ly + 8 * i]);
}

// ---------------------------------------------------------------------------
// fp16 GEMM, both operands half & K-major: C(MxN) = A(M,K) @ Bt(N,K)^T.
// BM=128 BN=128 BK=32; 256 threads = 8 warps (2m x 4n); warp tile 64x32.
// 3-stage cp.async pipeline; smem uint32(half2) units stride 20 ->
// every fragment LDS.32 bank-conflict-free (verified mapping).
// ---------------------------------------------------------------------------
template <int N, bool HALF_OUT>
__global__ __launch_bounds__(256) void gemm_hh(const __half* __restrict__ A,
                                               const __half* __restrict__ Bt,
                                               void* __restrict__ Cv) {
    constexpr int K = 2048;
    constexpr int NT = K / 32;
    extern __shared__ uint32_t smem[];
    uint32_t(*As)[128][20] = reinterpret_cast<uint32_t(*)[128][20]>(smem);
    uint32_t(*Bs)[128][20] =
        reinterpret_cast<uint32_t(*)[128][20]>(smem + 3 * 128 * 20);

    const int tid = threadIdx.x;
    const int lane = tid & 31, wid = tid >> 5;
    const int g = lane >> 2, t = lane & 3;
    const int wm = wid & 1, wn = wid >> 1;
    const int bm = blockIdx.y * 128, bn = blockIdx.x * 128;

    // loader mapping: each thread owns one (row, half-of-row)
    const int l_row = tid >> 1;          // 0..127
    const int l_u0  = (tid & 1) * 8;     // unit 0 or 8 (units are half2)

    const __half* gA = A + (size_t)(bm + l_row) * K + 2 * l_u0;
    const __half* gB = Bt + (size_t)(bn + l_row) * K + 2 * l_u0;

    float acc[4][4][4];
#pragma unroll
    for (int mi = 0; mi < 4; mi++)
#pragma unroll
        for (int ni = 0; ni < 4; ni++)
#pragma unroll
            for (int j = 0; j < 4; j++) acc[mi][ni][j] = 0.f;

    auto issue = [&](int kt) {
        int s = kt % 3;
        const __half* a = gA + kt * 32;
        cp16(sptr(&As[s][l_row][l_u0]), a);
        cp16(sptr(&As[s][l_row][l_u0 + 4]), a + 8);
        const __half* b = gB + kt * 32;
        cp16(sptr(&Bs[s][l_row][l_u0]), b);
        cp16(sptr(&Bs[s][l_row][l_u0 + 4]), b + 8);
        asm volatile("cp.async.commit_group;" ::: "memory");
    };

    issue(0);
    issue(1);

    for (int kt = 0; kt < NT; kt++) {
        if (kt + 1 < NT)
            asm volatile("cp.async.wait_group 1;" ::: "memory");
        else
            asm volatile("cp.async.wait_group 0;" ::: "memory");
        __syncthreads();
        if (kt + 2 < NT) issue(kt + 2);

        const int s = kt % 3;
#pragma unroll
        for (int ks = 0; ks < 2; ks++) {
            uint32_t aF[4][4];
#pragma unroll
            for (int mi = 0; mi < 4; mi++) {
                int r = wm * 64 + mi * 16;
                aF[mi][0] = As[s][r + g][ks * 8 + t];
                aF[mi][1] = As[s][r + g + 8][ks * 8 + t];
                aF[mi][2] = As[s][r + g][ks * 8 + t + 4];
                aF[mi][3] = As[s][r + g + 8][ks * 8 + t + 4];
            }
#pragma unroll
            for (int ni = 0; ni < 4; ni++) {
                int n = wn * 32 + ni * 8 + g;
                uint32_t bF[2];
                bF[0] = Bs[s][n][ks * 8 + t];
                bF[1] = Bs[s][n][ks * 8 + t + 4];
#pragma unroll
                for (int mi = 0; mi < 4; mi++) mma16(acc[mi][ni], aF[mi], bF);
            }
        }
        __syncthreads();
    }

    // epilogue
#pragma unroll
    for (int mi = 0; mi < 4; mi++) {
        int r0 = bm + wm * 64 + mi * 16 + g;
#pragma unroll
        for (int ni = 0; ni < 4; ni++) {
            int cN = bn + wn * 32 + ni * 8 + 2 * t;
            if (HALF_OUT) {
                __half* C = (__half*)Cv;
                *reinterpret_cast<__half2*>(C + (size_t)r0 * N + cN) =
                    __floats2half2_rn(acc[mi][ni][0], acc[mi][ni][1]);
                *reinterpret_cast<__half2*>(C + (size_t)(r0 + 8) * N + cN) =
                    __floats2half2_rn(acc[mi][ni][2], acc[mi][ni][3]);
            } else {
                float* C = (float*)Cv;
                *(float2*)(C + (size_t)r0 * N + cN) =
                    make_float2(acc[mi][ni][0], acc[mi][ni][1]);
                *(float2*)(C + (size_t)(r0 + 8) * N + cN) =
                    make_float2(acc[mi][ni][2], acc[mi][ni][3]);
            }
        }
    }
}

// ---------------------------------------------------------------------------
// V transpose: g_Vh (B*T, KV*D) half -> g_Vt (B,KV,D,T) half, key-pair packed.
// ---------------------------------------------------------------------------
__global__ __launch_bounds__(256) void transpose_v(const __half* __restrict__ Vh,
                                                   __half* __restrict__ Vt) {
    __shared__ uint32_t U[64][33];
    const int tid = threadIdx.x;
    const int k0 = blockIdx.x * 64;
    const int kv = blockIdx.y >> 1;
    const int d0 = (blockIdx.y & 1) * 64;
    const int b  = blockIdx.z;

    const uint32_t* in = reinterpret_cast<const uint32_t*>(Vh);
    {
        int dp = tid & 31;
        int krow = tid >> 5;
#pragma unroll
        for (int i = 0; i < 8; i++) {
            int key = i * 8 + krow;
            U[key][dp] =
                in[(size_t)(b * 2048 + k0 + key) * 256 + kv * 64 + (d0 >> 1) + dp];
        }
    }
    __syncthreads();
    uint32_t* out = reinterpret_cast<uint32_t*>(Vt);
    {
        int kp = tid & 31;
        int drow = tid >> 5;
#pragma unroll
        for (int i = 0; i < 8; i++) {
            int d = i * 8 + drow;
            uint32_t a = U[2 * kp][d >> 1];
            uint32_t c = U[2 * kp + 1][d >> 1];
            uint32_t lo = (d & 1) ? (a >> 16) : (a & 0xffffu);
            uint32_t hi = (d & 1) ? (c >> 16) : (c & 0xffffu);
            out[(size_t)((b * 4 + kv) * 128 + d0 + d) * 1024 + (k0 >> 1) + kp] =
                lo | (hi << 16);
        }
    }
}

// ---------------------------------------------------------------------------
// Flash attention (causal, GQA), fp16 m16n8k16 core, f32 softmax/accum.
// Grid (T/64, H, B), 128 threads = 4 warps; warp owns 16 query rows.
// uint4 global staging; half output for the downstream half GEMM.
// ---------------------------------------------------------------------------
struct AttnSmemH {
    uint32_t Qs[64][68];     // (row, d-pair)
    uint32_t Ks[32][68];     // (key, d-pair)
    uint32_t Vs[128][20];    // (d,  key-pair)
    uint32_t Ps[4][16][20];  // per-warp P tile
};

__global__ __launch_bounds__(128) void attn_f16(const __half* __restrict__ Qh,
                                                const __half* __restrict__ Kh,
                                                const __half* __restrict__ Vt,
                                                __half* __restrict__ Y) {
    __shared__ AttnSmemH S;

    const int b = blockIdx.z, h = blockIdx.y, qb = blockIdx.x;
    const int kv = h >> 2;  // G = 4
    const int tid = threadIdx.x, w = tid >> 5, lane = tid & 31;
    const int g = lane >> 2, t = lane & 3;
    const float scale = 0.08838834764831845f;  // 1/sqrt(128)

    const uint4* Qv = reinterpret_cast<const uint4*>(Qh);  // 8 half / unit
    const uint4* Kv = reinterpret_cast<const uint4*>(Kh);
    const uint4* Vv = reinterpret_cast<const uint4*>(Vt);

    // Stage Q block: 64 rows x 16 uint4
    {
        int r = tid >> 1, q = tid & 1;
        size_t base = (size_t)(b * 2048 + qb * 64 + r) * 256 + h * 16;
#pragma unroll
        for (int j = 0; j < 8; j++) {
            *(uint4*)&S.Qs[r][(q * 8 + j) * 4] = Qv[base + q * 8 + j];
        }
    }
    __syncthreads();

    // Q fragments register-resident: 8 k16-steps x 4 regs
    uint32_t qF[8][4];
#pragma unroll
    for (int ks = 0; ks < 8; ks++) {
        int r = w * 16;
        qF[ks][0] = S.Qs[r + g][ks * 8 + t];
        qF[ks][1] = S.Qs[r + g + 8][ks * 8 + t];
        qF[ks][2] = S.Qs[r + g][ks * 8 + t + 4];
        qF[ks][3] = S.Qs[r + g + 8][ks * 8 + t + 4];
    }

    float O[16][4];
#pragma unroll
    for (int i = 0; i < 16; i++)
#pragma unroll
        for (int j = 0; j < 4; j++) O[i][j] = 0.f;
    float m0 = -1e30f, m1 = -1e30f, l0 = 0.f, l1 = 0.f;

    const int qr0 = qb * 64 + w * 16 + g;
    const int qr1 = qr0 + 8;
    const int qmaxw = qb * 64 + w * 16 + 15;
    const int ntiles = qb * 2 + 2;  // keys 0 .. qb*64+63

    for (int jt = 0; jt < ntiles; jt++) {
        const int jbase = jt * 32;
        __syncthreads();  // previous tile fully consumed
        // K tile: 32 rows x 16 uint4
        {
            int r = tid >> 2, c = tid & 3;
            size_t base = (size_t)(b * 2048 + jbase + r) * 64 + kv * 16;
#pragma unroll
            for (int j = 0; j < 4; j++) {
                *(uint4*)&S.Ks[r][(c * 4 + j) * 4] = Kv[base + c * 4 + j];
            }
        }
        // V tile (transposed): 128 d-rows x 4 uint4
        {
            int d = tid;
            size_t base = (size_t)((b * 4 + kv) * 128 + d) * 256 + jt * 4;
#pragma unroll
            for (int j = 0; j < 4; j++) {
                *(uint4*)&S.Vs[d][j * 4] = Vv[base + j];
            }
        }
        __syncthreads();

        if (jbase > qmaxw) continue;  // tile fully masked for this warp

        // S = Q @ K^T  (16 x 32), 8 k16-steps
        float s[4][4];
#pragma unroll
        for (int ni = 0; ni < 4; ni++)
#pragma unroll
            for (int j = 0; j < 4; j++) s[ni][j] = 0.f;
#pragma unroll
        for (int ks = 0; ks < 8; ks++) {
#pragma unroll
            for (int ni = 0; ni < 4; ni++) {
                uint32_t bK[2];
                bK[0] = S.Ks[ni * 8 + g][ks * 8 + t];
                bK[1] = S.Ks[ni * 8 + g][ks * 8 + t + 4];
                mma16(s[ni], qF[ks], bK);
            }
        }

        // scale + causal mask
#pragma unroll
        for (int ni = 0; ni < 4; ni++) {
            int col = jbase + ni * 8 + 2 * t;
            s[ni][0] = (col     <= qr0) ? s[ni][0] * scale : -1e30f;
            s[ni][1] = (col + 1 <= qr0) ? s[ni][1] * scale : -1e30f;
            s[ni][2] = (col     <= qr1) ? s[ni][2] * scale : -1e30f;
            s[ni][3] = (col + 1 <= qr1) ? s[ni][3] * scale : -1e30f;
        }

        // online softmax row statistics
        float tm0 = -1e30f, tm1 = -1e30f;
#pragma unroll
        for (int ni = 0; ni < 4; ni++) {
            tm0 = fmaxf(tm0, fmaxf(s[ni][0], s[ni][1]));
            tm1 = fmaxf(tm1, fmaxf(s[ni][2], s[ni][3]));
        }
        tm0 = fmaxf(tm0, __shfl_xor_sync(0xffffffffu, tm0, 1));
        tm0 = fmaxf(tm0, __shfl_xor_sync(0xffffffffu, tm0, 2));
        tm1 = fmaxf(tm1, __shfl_xor_sync(0xffffffffu, tm1, 1));
        tm1 = fmaxf(tm1, __shfl_xor_sync(0xffffffffu, tm1, 2));
        float nm0 = fmaxf(m0, tm0), nm1 = fmaxf(m1, tm1);
        float corr0 = __expf(m0 - nm0), corr1 = __expf(m1 - nm1);

        float ls0 = 0.f, ls1 = 0.f;
#pragma unroll
        for (int ni = 0; ni < 4; ni++) {
            s[ni][0] = __expf(s[ni][0] - nm0);
            s[ni][1] = __expf(s[ni][1] - nm0);
            s[ni][2] = __expf(s[ni][2] - nm1);
            s[ni][3] = __expf(s[ni][3] - nm1);
            ls0 += s[ni][0] + s[ni][1];
            ls1 += s[ni][2] + s[ni][3];
        }
        ls0 += __shfl_xor_sync(0xffffffffu, ls0, 1);
        ls0 += __shfl_xor_sync(0xffffffffu, ls0, 2);
        ls1 += __shfl_xor_sync(0xffffffffu, ls1, 1);
        ls1 += __shfl_xor_sync(0xffffffffu, ls1, 2);
        l0 = l0 * corr0 + ls0;
        l1 = l1 * corr1 + ls1;
        m0 = nm0;
        m1 = nm1;

        // rescale O accumulator
#pragma unroll
        for (int nf = 0; nf < 16; nf++) {
            O[nf][0] *= corr0; O[nf][1] *= corr0;
            O[nf][2] *= corr1; O[nf][3] *= corr1;
        }

        // P (C-layout) -> per-warp smem (half2 key-pairs) -> A-layout frags
#pragma unroll
        for (int ni = 0; ni < 4; ni++) {
            S.Ps[w][g][ni * 4 + t]     = packh2(s[ni][0], s[ni][1]);
            S.Ps[w][g + 8][ni * 4 + t] = packh2(s[ni][2], s[ni][3]);
        }
        __syncwarp();

        // O += P @ V   (16x32 @ 32x128), 2 k16-steps
#pragma unroll
        for (int ks2 = 0; ks2 < 2; ks2++) {
            uint32_t aP[4];
            aP[0] = S.Ps[w][g][ks2 * 8 + t];
            aP[1] = S.Ps[w][g + 8][ks2 * 8 + t];
            aP[2] = S.Ps[w][g][ks2 * 8 + t + 4];
            aP[3] = S.Ps[w][g + 8][ks2 * 8 + t + 4];
#pragma unroll
            for (int nf = 0; nf < 16; nf++) {
                uint32_t bV[2];
                bV[0] = S.Vs[nf * 8 + g][ks2 * 8 + t];
                bV[1] = S.Vs[nf * 8 + g][ks2 * 8 + t + 4];
                mma16(O[nf], aP, bV);
            }
        }
    }

    // epilogue: normalize and store half (feeds half out-projection)
    __half* Yb = Y + ((size_t)(b * 2048 + qb * 64)) * 2048 + h * 128;
    float inv0 = 1.f / l0, inv1 = 1.f / l1;
#pragma unroll
    for (int nf = 0; nf < 16; nf++) {
        int cN = nf * 8 + 2 * t;
        *reinterpret_cast<__half2*>(Yb + (size_t)(w * 16 + g) * 2048 + cN) =
            __floats2half2_rn(O[nf][0] * inv0, O[nf][1] * inv0);
        *reinterpret_cast<__half2*>(Yb + (size_t)(w * 16 + g + 8) * 2048 + cN) =
            __floats2half2_rn(O[nf][2] * inv1, O[nf][3] * inv1);
    }
}

// ---------------------------------------------------------------------------
// Launch
// ---------------------------------------------------------------------------
extern "C" void kernel_launch(void* const* d_in, const int* in_sizes, int n_in,
                              void* d_out, int out_size) {
    (void)in_sizes; (void)n_in; (void)out_size;
    const float* x  = (const float*)d_in[0];
    const float* Wq = (const float*)d_in[1];
    const float* Wk = (const float*)d_in[2];
    const float* Wv = (const float*)d_in[3];
    const float* Wo = (const float*)d_in[4];
    float* out = (float*)d_out;

    __half *xh, *Wqt, *Wkt, *Wvt, *Wot, *Qp, *Kp, *Vp, *Vtp, *AYp;
    cudaGetSymbolAddress((void**)&xh,  g_xh);
    cudaGetSymbolAddress((void**)&Wqt, g_Wqt);
    cudaGetSymbolAddress((void**)&Wkt, g_Wkt);
    cudaGetSymbolAddress((void**)&Wvt, g_Wvt);
    cudaGetSymbolAddress((void**)&Wot, g_Wot);
    cudaGetSymbolAddress((void**)&Qp,  g_Qh);
    cudaGetSymbolAddress((void**)&Kp,  g_Kh);
    cudaGetSymbolAddress((void**)&Vp,  g_Vh);
    cudaGetSymbolAddress((void**)&Vtp, g_Vt);
    cudaGetSymbolAddress((void**)&AYp, g_AYh);

    const int SMEM_GEMM = 3 * 128 * 20 * 4 * 2;  // 61440 B
    cudaFuncSetAttribute(gemm_hh<2048, true>,
                         cudaFuncAttributeMaxDynamicSharedMemorySize, SMEM_GEMM);
    cudaFuncSetAttribute(gemm_hh<512, true>,
                         cudaFuncAttributeMaxDynamicSharedMemorySize, SMEM_GEMM);
    cudaFuncSetAttribute(gemm_hh<2048, false>,
                         cudaFuncAttributeMaxDynamicSharedMemorySize, SMEM_GEMM);

    // Stage 0: precision prep (x -> half, weights -> transposed half)
    f2h_kernel<<<4 * 2048 * 2048 / 1024, 256>>>(x, xh);
    transpose_w<<<dim3(64, 64), 256>>>(Wq, Wqt, 2048);
    transpose_w<<<dim3(16, 64), 256>>>(Wk, Wkt, 512);
    transpose_w<<<dim3(16, 64), 256>>>(Wv, Wvt, 512);
    transpose_w<<<dim3(64, 64), 256>>>(Wo, Wot, 2048);

    // Stage 1: QKV projections (M=8192, K=2048), half outputs
    gemm_hh<2048, true><<<dim3(16, 64), 256, SMEM_GEMM>>>(xh, Wqt, Qp);
    gemm_hh<512, true><<<dim3(4, 64), 256, SMEM_GEMM>>>(xh, Wkt, Kp);
    gemm_hh<512, true><<<dim3(4, 64), 256, SMEM_GEMM>>>(xh, Wvt, Vp);

    // Stage 1b: transpose V into (B,KV,D,T) key-pair-packed layout
    transpose_v<<<dim3(32, 8, 4), 256>>>(Vp, Vtp);

    // Stage 2: causal GQA flash attention (fp16 core, f32 softmax)
    attn_f16<<<dim3(32, 16, 4), 128>>>(Qp, Kp, Vtp, AYp);

    // Stage 3: output projection (half in, f32 out)
    gemm_hh<2048, false><<<dim3(16, 64), 256, SMEM_GEMM>>>(AYp, Wot, out);
}

// round 8
// speedup vs baseline: 1.8564x; 1.1004x over previous
#include <cuda_runtime.h>
#include <cuda_fp16.h>
#include <cstdint>

#define DEV_INLINE __device__ __forceinline__

// ---------------------------------------------------------------------------
// Problem constants: B=4, T=2048, E=2048, H=16, KV=4, G=4, D=128
// Fused QKV width: H*D + 2*KV*D = 2048 + 512 + 512 = 3072
// ---------------------------------------------------------------------------

// Scratch (device-global: allocation-free per harness rules)
__device__ __half g_xh  [4 * 2048 * 2048];     // x half             32 MB
__device__ __half g_Wf  [3072 * 2048];         // [Wq;Wk;Wv]^T half  12 MB
__device__ __half g_Wot [2048 * 2048];         // Wo^T half           8 MB
__device__ __half g_QKV [4 * 2048 * 3072];     // fused QKV out      48 MB
__device__ __half g_Vt  [4 * 4 * 128 * 2048];  // (B,KV,D,T)          8 MB
__device__ __half g_AYh [4 * 2048 * 2048];     // attn out half      32 MB

DEV_INLINE uint32_t packh2(float lo, float hi) {
    __half2 h = __floats2half2_rn(lo, hi);
    return *reinterpret_cast<uint32_t*>(&h);
}

DEV_INLINE void mma16(float* c, const uint32_t* a, const uint32_t* b) {
    asm("mma.sync.aligned.m16n8k16.row.col.f32.f16.f16.f32 "
        "{%0,%1,%2,%3}, {%4,%5,%6,%7}, {%8,%9}, {%0,%1,%2,%3};"
        : "+f"(c[0]), "+f"(c[1]), "+f"(c[2]), "+f"(c[3])
        : "r"(a[0]), "r"(a[1]), "r"(a[2]), "r"(a[3]), "r"(b[0]), "r"(b[1]));
}

DEV_INLINE uint32_t sptr(const void* p) {
    return (uint32_t)__cvta_generic_to_shared(p);
}
DEV_INLINE void cp16(uint32_t dst, const void* src) {
    asm volatile("cp.async.cg.shared.global [%0], [%1], 16;" ::
                     "r"(dst), "l"(src));
}
DEV_INLINE void ldsm4(uint32_t* r, uint32_t addr) {
    asm volatile("ldmatrix.sync.aligned.m8n8.x4.shared.b16 {%0,%1,%2,%3}, [%4];"
                 : "=r"(r[0]), "=r"(r[1]), "=r"(r[2]), "=r"(r[3])
                 : "r"(addr));
}

// ---------------------------------------------------------------------------
// Prep kernels
// ---------------------------------------------------------------------------
__global__ __launch_bounds__(256) void f2h_kernel(const float* __restrict__ in,
                                                  __half* __restrict__ out) {
    int i = (blockIdx.x * 256 + threadIdx.x) * 4;
    float4 v = *(const float4*)(in + i);
    uint2 o;
    o.x = packh2(v.x, v.y);
    o.y = packh2(v.z, v.w);
    *(uint2*)(out + i) = o;
}

// W (K=2048, N) f32 -> Wt (N, K=2048) half. Tile 32x32, block 256.
__global__ __launch_bounds__(256) void transpose_w(const float* __restrict__ W,
                                                   __half* __restrict__ Wt,
                                                   int Ncols) {
    __shared__ float t[32][33];
    const int n0 = blockIdx.x * 32, k0 = blockIdx.y * 32;
    const int lx = threadIdx.x & 31, ly = threadIdx.x >> 5;  // ly 0..7
#pragma unroll
    for (int i = 0; i < 4; i++)
        t[ly + 8 * i][lx] = W[(size_t)(k0 + ly + 8 * i) * Ncols + n0 + lx];
    __syncthreads();
#pragma unroll
    for (int i = 0; i < 4; i++)
        Wt[(size_t)(n0 + ly + 8 * i) * 2048 + k0 + lx] =
            __float2half(t[lx][ly + 8 * i]);
}

// ---------------------------------------------------------------------------
// fp16 GEMM, both operands half & K-major: C(MxN) = A(M,K) @ Bt(N,K)^T.
// BM=128 BN=128 BK=32; 256 threads = 8 warps (2m x 4n); warp tile 64x32.
// 3-stage cp.async pipeline, ONE barrier per iteration, ldmatrix fragments.
// smem uint32(half2) units stride 20 (80 B rows): ldmatrix phases hit all
// 32 banks exactly once (rows 0..7 -> bank starts 0,20,8,28,16,4,24,12).
// ---------------------------------------------------------------------------
template <int N, bool HALF_OUT>
__global__ __launch_bounds__(256) void gemm_hh(const __half* __restrict__ A,
                                               const __half* __restrict__ Bt,
                                               void* __restrict__ Cv) {
    constexpr int K = 2048;
    constexpr int NT = K / 32;
    constexpr int STG = 128 * 20;  // uint32 units per stage per operand
    extern __shared__ uint32_t smem[];

    const int tid = threadIdx.x;
    const int lane = tid & 31, wid = tid >> 5;
    const int g = lane >> 2, t = lane & 3;
    const int wm = wid & 1, wn = wid >> 1;
    const int bm = blockIdx.y * 128, bn = blockIdx.x * 128;

    // loader mapping: each thread owns one (row, half-of-row)
    const int l_row = tid >> 1;       // 0..127
    const int l_u0  = (tid & 1) * 8;  // unit 0 or 8

    const __half* gA = A + (size_t)(bm + l_row) * K + 2 * l_u0;
    const __half* gB = Bt + (size_t)(bn + l_row) * K + 2 * l_u0;

    const uint32_t sA = sptr(smem);
    const uint32_t sB = sA + 3 * STG * 4;
    const uint32_t stA = sA + l_row * 80 + l_u0 * 4;
    const uint32_t stB = sB + l_row * 80 + l_u0 * 4;

    // ldmatrix lane addresses
    const uint32_t aAddr =
        sA + (wm * 64 + (lane & 7) + ((lane >> 3) & 1) * 8) * 80 +
        ((lane >> 4) * 4) * 4;
    const uint32_t bAddr =
        sB + (wn * 32 + (lane & 7) + ((lane >> 4) & 1) * 8) * 80 +
        (((lane >> 3) & 1) * 4) * 4;

    float acc[4][4][4];
#pragma unroll
    for (int mi = 0; mi < 4; mi++)
#pragma unroll
        for (int ni = 0; ni < 4; ni++)
#pragma unroll
            for (int j = 0; j < 4; j++) acc[mi][ni][j] = 0.f;

    auto issue = [&](int kt) {
        const uint32_t off = (kt % 3) * STG * 4;
        const __half* a = gA + kt * 32;
        cp16(stA + off, a);
        cp16(stA + off + 16, a + 8);
        const __half* b = gB + kt * 32;
        cp16(stB + off, b);
        cp16(stB + off + 16, b + 8);
        asm volatile("cp.async.commit_group;" ::: "memory");
    };

    issue(0);
    issue(1);

    for (int kt = 0; kt < NT; kt++) {
        if (kt + 1 < NT)
            asm volatile("cp.async.wait_group 1;" ::: "memory");
        else
            asm volatile("cp.async.wait_group 0;" ::: "memory");
        __syncthreads();
        if (kt + 2 < NT) issue(kt + 2);

        const uint32_t soff = (kt % 3) * STG * 4;
#pragma unroll
        for (int ks = 0; ks < 2; ks++) {
            uint32_t aF[4][4], bF[2][4];
#pragma unroll
            for (int mi = 0; mi < 4; mi++)
                ldsm4(aF[mi], aAddr + soff + mi * 16 * 80 + ks * 32);
            ldsm4(bF[0], bAddr + soff + ks * 32);
            ldsm4(bF[1], bAddr + soff + 16 * 80 + ks * 32);
#pragma unroll
            for (int ni = 0; ni < 4; ni++) {
                const uint32_t* bp = &bF[ni >> 1][(ni & 1) * 2];
#pragma unroll
                for (int mi = 0; mi < 4; mi++) mma16(acc[mi][ni], aF[mi], bp);
            }
        }
    }

    // epilogue
#pragma unroll
    for (int mi = 0; mi < 4; mi++) {
        int r0 = bm + wm * 64 + mi * 16 + g;
#pragma unroll
        for (int ni = 0; ni < 4; ni++) {
            int cN = bn + wn * 32 + ni * 8 + 2 * t;
            if (HALF_OUT) {
                __half* C = (__half*)Cv;
                *reinterpret_cast<__half2*>(C + (size_t)r0 * N + cN) =
                    __floats2half2_rn(acc[mi][ni][0], acc[mi][ni][1]);
                *reinterpret_cast<__half2*>(C + (size_t)(r0 + 8) * N + cN) =
                    __floats2half2_rn(acc[mi][ni][2], acc[mi][ni][3]);
            } else {
                float* C = (float*)Cv;
                *(float2*)(C + (size_t)r0 * N + cN) =
                    make_float2(acc[mi][ni][0], acc[mi][ni][1]);
                *(float2*)(C + (size_t)(r0 + 8) * N + cN) =
                    make_float2(acc[mi][ni][2], acc[mi][ni][3]);
            }
        }
    }
}

// ---------------------------------------------------------------------------
// V transpose: V slice of fused QKV (row stride 3072) -> g_Vt (B,KV,D,T),
// key-pair packed half2.
// ---------------------------------------------------------------------------
__global__ __launch_bounds__(256) void transpose_v(const __half* __restrict__ C,
                                                   __half* __restrict__ Vt) {
    __shared__ uint32_t U[64][33];
    const int tid = threadIdx.x;
    const int k0 = blockIdx.x * 64;
    const int kv = blockIdx.y >> 1;
    const int d0 = (blockIdx.y & 1) * 64;
    const int b  = blockIdx.z;

    const uint32_t* in = reinterpret_cast<const uint32_t*>(C);
    {
        int dp = tid & 31;
        int krow = tid >> 5;
#pragma unroll
        for (int i = 0; i < 8; i++) {
            int key = i * 8 + krow;
            U[key][dp] = in[(size_t)(b * 2048 + k0 + key) * 1536 + 1280 +
                            kv * 64 + (d0 >> 1) + dp];
        }
    }
    __syncthreads();
    uint32_t* out = reinterpret_cast<uint32_t*>(Vt);
    {
        int kp = tid & 31;
        int drow = tid >> 5;
#pragma unroll
        for (int i = 0; i < 8; i++) {
            int d = i * 8 + drow;
            uint32_t a = U[2 * kp][d >> 1];
            uint32_t c = U[2 * kp + 1][d >> 1];
            uint32_t lo = (d & 1) ? (a >> 16) : (a & 0xffffu);
            uint32_t hi = (d & 1) ? (c >> 16) : (c & 0xffffu);
            out[(size_t)((b * 4 + kv) * 128 + d0 + d) * 1024 + (k0 >> 1) + kp] =
                lo | (hi << 16);
        }
    }
}

// ---------------------------------------------------------------------------
// Flash attention (causal, GQA), fp16 m16n8k16 core, f32 softmax/accum.
// Grid (T/64, H, B), 128 threads = 4 warps; warp owns 16 query rows.
// All fragment loads via ldmatrix.x4 (conflict-free: strides 272 B / 80 B).
// Reads Q,K from fused QKV (row stride 3072); V from transposed g_Vt.
// ---------------------------------------------------------------------------
struct AttnSmemH {
    uint32_t Qs[64][68];     // (row, d-pair)   272 B rows
    uint32_t Ks[32][68];     // (key, d-pair)
    uint32_t Vs[128][20];    // (d,  key-pair)   80 B rows
    uint32_t Ps[4][16][20];  // per-warp P tile
};

__global__ __launch_bounds__(128) void attn_f16(const __half* __restrict__ Cqkv,
                                                const __half* __restrict__ Vt,
                                                __half* __restrict__ Y) {
    __shared__ AttnSmemH S;

    const int b = blockIdx.z, h = blockIdx.y, qb = blockIdx.x;
    const int kv = h >> 2;  // G = 4
    const int tid = threadIdx.x, w = tid >> 5, lane = tid & 31;
    const int g = lane >> 2, t = lane & 3;
    const float scale = 0.08838834764831845f;  // 1/sqrt(128)

    const uint4* Cv = reinterpret_cast<const uint4*>(Cqkv);  // 8 half / unit
    const uint4* Vv = reinterpret_cast<const uint4*>(Vt);

    // ldmatrix lane addresses
    const uint32_t qAddr =
        sptr(S.Qs) + (w * 16 + (lane & 7) + ((lane >> 3) & 1) * 8) * 272 +
        ((lane >> 4) * 4) * 4;
    const uint32_t kAddr =
        sptr(S.Ks) + ((lane & 7) + ((lane >> 4) & 1) * 8) * 272 +
        (((lane >> 3) & 1) * 4) * 4;
    const uint32_t vAddr =
        sptr(S.Vs) + ((lane & 7) + ((lane >> 4) & 1) * 8) * 80 +
        (((lane >> 3) & 1) * 4) * 4;
    const uint32_t pAddr =
        sptr(&S.Ps[w][0][0]) + ((lane & 7) + ((lane >> 3) & 1) * 8) * 80 +
        ((lane >> 4) * 4) * 4;

    // Stage Q block: 64 rows x 16 uint4 (row stride 3072 half = 384 uint4)
    {
        int r = tid >> 1, q = tid & 1;
        size_t base = (size_t)(b * 2048 + qb * 64 + r) * 384 + h * 16;
#pragma unroll
        for (int j = 0; j < 8; j++) {
            *(uint4*)&S.Qs[r][(q * 8 + j) * 4] = Cv[base + q * 8 + j];
        }
    }
    __syncthreads();

    // Q fragments register-resident: 8 k16-steps x 4 regs (ldmatrix)
    uint32_t qF[8][4];
#pragma unroll
    for (int ks = 0; ks < 8; ks++) ldsm4(qF[ks], qAddr + ks * 32);

    float O[16][4];
#pragma unroll
    for (int i = 0; i < 16; i++)
#pragma unroll
        for (int j = 0; j < 4; j++) O[i][j] = 0.f;
    float m0 = -1e30f, m1 = -1e30f, l0 = 0.f, l1 = 0.f;

    const int qr0 = qb * 64 + w * 16 + g;
    const int qr1 = qr0 + 8;
    const int qmaxw = qb * 64 + w * 16 + 15;
    const int ntiles = qb * 2 + 2;  // keys 0 .. qb*64+63

    for (int jt = 0; jt < ntiles; jt++) {
        const int jbase = jt * 32;
        __syncthreads();  // previous tile fully consumed
        // K tile: 32 rows x 8 uint4 (K slice offset 2048 half = 256 uint4)
        {
            int r = tid >> 2, c = tid & 3;
            size_t base = (size_t)(b * 2048 + jbase + r) * 384 + 256 + kv * 16;
#pragma unroll
            for (int j = 0; j < 4; j++) {
                *(uint4*)&S.Ks[r][(c * 4 + j) * 4] = Cv[base + c * 4 + j];
            }
        }
        // V tile (transposed): 128 d-rows x 4 uint4
        {
            int d = tid;
            size_t base = (size_t)((b * 4 + kv) * 128 + d) * 256 + jt * 4;
#pragma unroll
            for (int j = 0; j < 4; j++) {
                *(uint4*)&S.Vs[d][j * 4] = Vv[base + j];
            }
        }
        __syncthreads();

        if (jbase > qmaxw) continue;  // tile fully masked for this warp

        // S = Q @ K^T  (16 x 32), 8 k16-steps, K-frags via ldmatrix
        float s[4][4];
#pragma unroll
        for (int ni = 0; ni < 4; ni++)
#pragma unroll
            for (int j = 0; j < 4; j++) s[ni][j] = 0.f;
#pragma unroll
        for (int ks = 0; ks < 8; ks++) {
            uint32_t kA[4], kB[4];
            ldsm4(kA, kAddr + ks * 32);
            ldsm4(kB, kAddr + 16 * 272 + ks * 32);
            mma16(s[0], qF[ks], kA);
            mma16(s[1], qF[ks], kA + 2);
            mma16(s[2], qF[ks], kB);
            mma16(s[3], qF[ks], kB + 2);
        }

        // scale + causal mask
#pragma unroll
        for (int ni = 0; ni < 4; ni++) {
            int col = jbase + ni * 8 + 2 * t;
            s[ni][0] = (col     <= qr0) ? s[ni][0] * scale : -1e30f;
            s[ni][1] = (col + 1 <= qr0) ? s[ni][1] * scale : -1e30f;
            s[ni][2] = (col     <= qr1) ? s[ni][2] * scale : -1e30f;
            s[ni][3] = (col + 1 <= qr1) ? s[ni][3] * scale : -1e30f;
        }

        // online softmax row statistics
        float tm0 = -1e30f, tm1 = -1e30f;
#pragma unroll
        for (int ni = 0; ni < 4; ni++) {
            tm0 = fmaxf(tm0, fmaxf(s[ni][0], s[ni][1]));
            tm1 = fmaxf(tm1, fmaxf(s[ni][2], s[ni][3]));
        }
        tm0 = fmaxf(tm0, __shfl_xor_sync(0xffffffffu, tm0, 1));
        tm0 = fmaxf(tm0, __shfl_xor_sync(0xffffffffu, tm0, 2));
        tm1 = fmaxf(tm1, __shfl_xor_sync(0xffffffffu, tm1, 1));
        tm1 = fmaxf(tm1, __shfl_xor_sync(0xffffffffu, tm1, 2));
        float nm0 = fmaxf(m0, tm0), nm1 = fmaxf(m1, tm1);
        float corr0 = __expf(m0 - nm0), corr1 = __expf(m1 - nm1);

        float ls0 = 0.f, ls1 = 0.f;
#pragma unroll
        for (int ni = 0; ni < 4; ni++) {
            s[ni][0] = __expf(s[ni][0] - nm0);
            s[ni][1] = __expf(s[ni][1] - nm0);
            s[ni][2] = __expf(s[ni][2] - nm1);
            s[ni][3] = __expf(s[ni][3] - nm1);
            ls0 += s[ni][0] + s[ni][1];
            ls1 += s[ni][2] + s[ni][3];
        }
        ls0 += __shfl_xor_sync(0xffffffffu, ls0, 1);
        ls0 += __shfl_xor_sync(0xffffffffu, ls0, 2);
        ls1 += __shfl_xor_sync(0xffffffffu, ls1, 1);
        ls1 += __shfl_xor_sync(0xffffffffu, ls1, 2);
        l0 = l0 * corr0 + ls0;
        l1 = l1 * corr1 + ls1;
        m0 = nm0;
        m1 = nm1;

        // rescale O accumulator
#pragma unroll
        for (int nf = 0; nf < 16; nf++) {
            O[nf][0] *= corr0; O[nf][1] *= corr0;
            O[nf][2] *= corr1; O[nf][3] *= corr1;
        }

        // P (C-layout) -> per-warp smem (half2 key-pairs) -> A-layout frags
#pragma unroll
        for (int ni = 0; ni < 4; ni++) {
            S.Ps[w][g][ni * 4 + t]     = packh2(s[ni][0], s[ni][1]);
            S.Ps[w][g + 8][ni * 4 + t] = packh2(s[ni][2], s[ni][3]);
        }
        __syncwarp();

        // O += P @ V   (16x32 @ 32x128), 2 k16-steps, frags via ldmatrix
#pragma unroll
        for (int ks2 = 0; ks2 < 2; ks2++) {
            uint32_t aP[4];
            ldsm4(aP, pAddr + ks2 * 32);
#pragma unroll
            for (int nj = 0; nj < 8; nj++) {
                uint32_t vF[4];
                ldsm4(vF, vAddr + nj * 16 * 80 + ks2 * 32);
                mma16(O[nj * 2], aP, vF);
                mma16(O[nj * 2 + 1], aP, vF + 2);
            }
        }
    }

    // epilogue: normalize and store half (feeds half out-projection)
    __half* Yb = Y + ((size_t)(b * 2048 + qb * 64)) * 2048 + h * 128;
    float inv0 = 1.f / l0, inv1 = 1.f / l1;
#pragma unroll
    for (int nf = 0; nf < 16; nf++) {
        int cN = nf * 8 + 2 * t;
        *reinterpret_cast<__half2*>(Yb + (size_t)(w * 16 + g) * 2048 + cN) =
            __floats2half2_rn(O[nf][0] * inv0, O[nf][1] * inv0);
        *reinterpret_cast<__half2*>(Yb + (size_t)(w * 16 + g + 8) * 2048 + cN) =
            __floats2half2_rn(O[nf][2] * inv1, O[nf][3] * inv1);
    }
}

// ---------------------------------------------------------------------------
// Launch
// ---------------------------------------------------------------------------
extern "C" void kernel_launch(void* const* d_in, const int* in_sizes, int n_in,
                              void* d_out, int out_size) {
    (void)in_sizes; (void)n_in; (void)out_size;
    const float* x  = (const float*)d_in[0];
    const float* Wq = (const float*)d_in[1];
    const float* Wk = (const float*)d_in[2];
    const float* Wv = (const float*)d_in[3];
    const float* Wo = (const float*)d_in[4];
    float* out = (float*)d_out;

    __half *xh, *Wf, *Wot, *Cqkv, *Vtp, *AYp;
    cudaGetSymbolAddress((void**)&xh,   g_xh);
    cudaGetSymbolAddress((void**)&Wf,   g_Wf);
    cudaGetSymbolAddress((void**)&Wot,  g_Wot);
    cudaGetSymbolAddress((void**)&Cqkv, g_QKV);
    cudaGetSymbolAddress((void**)&Vtp,  g_Vt);
    cudaGetSymbolAddress((void**)&AYp,  g_AYh);

    const int SMEM_GEMM = 6 * 128 * 20 * 4;  // 61440 B (3 stages x A,B)
    cudaFuncSetAttribute(gemm_hh<3072, true>,
                         cudaFuncAttributeMaxDynamicSharedMemorySize, SMEM_GEMM);
    cudaFuncSetAttribute(gemm_hh<2048, false>,
                         cudaFuncAttributeMaxDynamicSharedMemorySize, SMEM_GEMM);

    // Stage 0: prep (x -> half; weights -> fused transposed half)
    f2h_kernel<<<4 * 2048 * 2048 / 1024, 256>>>(x, xh);
    transpose_w<<<dim3(64, 64), 256>>>(Wq, Wf, 2048);
    transpose_w<<<dim3(16, 64), 256>>>(Wk, Wf + (size_t)2048 * 2048, 512);
    transpose_w<<<dim3(16, 64), 256>>>(Wv, Wf + (size_t)2560 * 2048, 512);
    transpose_w<<<dim3(64, 64), 256>>>(Wo, Wot, 2048);

    // Stage 1: fused QKV projection (M=8192, N=3072, K=2048)
    gemm_hh<3072, true><<<dim3(24, 64), 256, SMEM_GEMM>>>(xh, Wf, Cqkv);

    // Stage 1b: transpose V slice into (B,KV,D,T) key-pair-packed layout
    transpose_v<<<dim3(32, 8, 4), 256>>>(Cqkv, Vtp);

    // Stage 2: causal GQA flash attention (fp16 core, f32 softmax)
    attn_f16<<<dim3(32, 16, 4), 128>>>(Cqkv, Vtp, AYp);

    // Stage 3: output projection (half in, f32 out)
    gemm_hh<2048, false><<<dim3(16, 64), 256, SMEM_GEMM>>>(AYp, Wot, out);
}